// round 4
// baseline (speedup 1.0000x reference)
#include <cuda_runtime.h>
#include <cuda_fp16.h>
#include <cstdint>

#define DINL __device__ __forceinline__

namespace {
constexpr int Tn = 187;
constexpr int Hn = 256;
constexpr int BM = 128;          // batch rows per CTA
constexpr int NT = 256;          // threads per CTA (8 warps x 16 rows)

constexpr int WH_STRIDE = 528;   // bytes per Wh row (264 f16: 512 + 16 pad -> conflict-free ldsm)
constexpr int W1_STRIDE = 144;   // bytes per W1 row (72 f16)
constexpr int X_STRIDE  = 192;   // f16 per x row

constexpr int OFF_WH  = 0;
constexpr int OFF_W1  = OFF_WH + Hn * WH_STRIDE;        // 135168
constexpr int OFF_X   = OFF_W1 + Hn * W1_STRIDE;        // 172032
constexpr int OFF_WXB = OFF_X  + BM * X_STRIDE * 2;     // 221184  (float2 {Wx,b} x256)
constexpr int OFF_B1  = OFF_WXB + Hn * 8;               // 223232
constexpr int OFF_W2  = OFF_B1 + 64 * 4;                // 223488
constexpr int OFF_B2  = OFF_W2 + 320 * 4;               // 224768
constexpr int SMEM_TOTAL = OFF_B2 + 32;                 // 224800
static_assert(SMEM_TOTAL <= 232448, "smem overflow");
}

// ---------------- helpers ----------------
DINL uint32_t smem_u32(const void* p) {
    uint32_t a;
    asm("{ .reg .u64 t; cvta.to.shared.u64 t, %1; cvt.u32.u64 %0, t; }" : "=r"(a) : "l"(p));
    return a;
}
// ldmatrix x4 transposed (B fragments for row.col mma from k-major smem)
DINL void ldsm4t(uint32_t& r0, uint32_t& r1, uint32_t& r2, uint32_t& r3, uint32_t addr) {
    asm volatile("ldmatrix.sync.aligned.m8n8.x4.trans.shared.b16 {%0,%1,%2,%3}, [%4];"
                 : "=r"(r0), "=r"(r1), "=r"(r2), "=r"(r3) : "r"(addr));
}
// D += A * B   (m16n8k16, f16 in, f32 accum)
DINL void mma16816(float* d, uint32_t a0, uint32_t a1, uint32_t a2, uint32_t a3,
                   uint32_t b0, uint32_t b1) {
    asm volatile("mma.sync.aligned.m16n8k16.row.col.f32.f16.f16.f32 "
                 "{%0,%1,%2,%3}, {%4,%5,%6,%7}, {%8,%9}, {%0,%1,%2,%3};"
                 : "+f"(d[0]), "+f"(d[1]), "+f"(d[2]), "+f"(d[3])
                 : "r"(a0), "r"(a1), "r"(a2), "r"(a3), "r"(b0), "r"(b1));
}
// accurate tanh: 1 - 2/(exp(2v)+1); ex2+rcp approx err ~1e-7
DINL float tanh_ev(float v) {
    v = fminf(fmaxf(v, -10.f), 10.f);
    float e, r;
    asm("ex2.approx.f32 %0, %1;" : "=f"(e) : "f"(v * 2.885390081777927f)); // 2*log2(e)
    asm("rcp.approx.f32 %0, %1;" : "=f"(r) : "f"(e + 1.f));
    return fmaf(-2.f, r, 1.f);
}
// pack {lo, hi} -> f16x2 (lo in bits[0:16))
DINL uint32_t pack_f16x2(float lo, float hi) {
    uint32_t r;
    asm("cvt.rn.f16x2.f32 %0, %1, %2;" : "=r"(r) : "f"(hi), "f"(lo));
    return r;
}

// ---------------- kernel ----------------
__global__ void __launch_bounds__(NT, 1)
rnn_kernel(const float* __restrict__ gx,  const float* __restrict__ gWx,
           const float* __restrict__ gWh, const float* __restrict__ gbr,
           const float* __restrict__ gW1, const float* __restrict__ gb1,
           const float* __restrict__ gW2, const float* __restrict__ gb2,
           float* __restrict__ gout) {
    extern __shared__ char smem[];
    const int tid  = threadIdx.x;
    const int lane = tid & 31;
    const int wid  = tid >> 5;
    const int m0   = blockIdx.x * BM;
    const int gid  = lane >> 2;      // row group 0..7
    const int tig  = lane & 3;       // thread-in-group

    // ---- cooperative staging ----
    for (int i = tid; i < Hn * Hn; i += NT) {            // Wh[k][n] -> k-major padded f16
        int k = i >> 8, n = i & 255;
        *(__half*)(smem + OFF_WH + k * WH_STRIDE + n * 2) = __float2half(gWh[i]);
    }
    for (int i = tid; i < Hn * 64; i += NT) {            // W1[k][n]
        int k = i >> 6, n = i & 63;
        *(__half*)(smem + OFF_W1 + k * W1_STRIDE + n * 2) = __float2half(gW1[i]);
    }
    for (int i = tid; i < BM * Tn; i += NT) {            // x tile, f16
        int r = i / Tn, t = i - r * Tn;
        ((__half*)(smem + OFF_X))[r * X_STRIDE + t] = __float2half(gx[(size_t)(m0 + r) * Tn + t]);
    }
    for (int i = tid; i < Hn; i += NT)
        ((float2*)(smem + OFF_WXB))[i] = make_float2(gWx[i], gbr[i]);
    for (int i = tid; i < 64; i += NT)  ((float*)(smem + OFF_B1))[i] = gb1[i];
    for (int i = tid; i < 320; i += NT) ((float*)(smem + OFF_W2))[i] = gW2[i];
    if (tid < 5) ((float*)(smem + OFF_B2))[tid] = gb2[tid];
    __syncthreads();   // the ONLY barrier in the kernel

    // ---- per-warp setup ----
    const uint32_t sb = smem_u32(smem);
    const int tq = lane >> 3;   // ldmatrix x4 slot: 0:(k,n0) 1:(k+8,n0) 2:(k,n0+8) 3:(k+8,n0+8)
    const uint32_t lds_wh = sb + OFF_WH + ((tq & 1) * 8 + (lane & 7)) * WH_STRIDE + (tq >> 1) * 16;
    const uint32_t lds_w1 = sb + OFF_W1 + ((tq & 1) * 8 + (lane & 7)) * W1_STRIDE + (tq >> 1) * 16;
    const __half* xr0 = (const __half*)(smem + OFF_X) + (wid * 16 + gid) * X_STRIDE;
    const __half* xr8 = xr0 + 8 * X_STRIDE;
    const float4* wxb4 = (const float4*)(smem + OFF_WXB);   // [wc, bc, wc1, bc1] at even c/2

    uint32_t hA[64];   // h as A fragments: hA[2t]=(row g, cols 8t+2tig..+1), hA[2t+1]=(row g+8)

    // ---- t = 0: h0 = tanh(x0*Wx + b) ----
    {
        float xg = __half2float(xr0[0]), xg8 = __half2float(xr8[0]);
        #pragma unroll
        for (int t2 = 0; t2 < 32; ++t2) {
            float4 wb = wxb4[(8 * t2 + 2 * tig) >> 1];   // (w0,b0,w1,b1)
            hA[2 * t2]     = pack_f16x2(tanh_ev(fmaf(xg,  wb.x, wb.y)),
                                        tanh_ev(fmaf(xg,  wb.z, wb.w)));
            hA[2 * t2 + 1] = pack_f16x2(tanh_ev(fmaf(xg8, wb.x, wb.y)),
                                        tanh_ev(fmaf(xg8, wb.z, wb.w)));
        }
    }

    // ---- recurrence: t = 1..186 (warp-private, no sync) ----
    #pragma unroll 1
    for (int t = 1; t < Tn; ++t) {
        float xg = __half2float(xr0[t]), xg8 = __half2float(xr8[t]);
        float d[32][4];
        #pragma unroll
        for (int t2 = 0; t2 < 32; ++t2) {               // D init = x_t*Wx + b (folds epilogue add)
            float4 wb = wxb4[(8 * t2 + 2 * tig) >> 1];
            d[t2][0] = fmaf(xg,  wb.x, wb.y);
            d[t2][1] = fmaf(xg,  wb.z, wb.w);
            d[t2][2] = fmaf(xg8, wb.x, wb.y);
            d[t2][3] = fmaf(xg8, wb.z, wb.w);
        }
        #pragma unroll
        for (int kc = 0; kc < 16; ++kc) {
            const uint32_t a0 = hA[4 * kc], a1 = hA[4 * kc + 1];
            const uint32_t a2 = hA[4 * kc + 2], a3 = hA[4 * kc + 3];
            const uint32_t base = lds_wh + kc * 16 * WH_STRIDE;
            #pragma unroll
            for (int nt2 = 0; nt2 < 16; ++nt2) {
                uint32_t b0, b1, b2, b3;
                ldsm4t(b0, b1, b2, b3, base + nt2 * 32);
                mma16816(d[2 * nt2],     a0, a1, a2, a3, b0, b1);
                mma16816(d[2 * nt2 + 1], a0, a1, a2, a3, b2, b3);
            }
        }
        #pragma unroll
        for (int t2 = 0; t2 < 32; ++t2) {               // tanh + repack as next-step A frags
            hA[2 * t2]     = pack_f16x2(tanh_ev(d[t2][0]), tanh_ev(d[t2][1]));
            hA[2 * t2 + 1] = pack_f16x2(tanh_ev(d[t2][2]), tanh_ev(d[t2][3]));
        }
    }

    // ---- head: hidden = relu(h @ W1 + b1) via mma, then W2 + softmax per thread ----
    float hd[8][4];
    #pragma unroll
    for (int t2 = 0; t2 < 8; ++t2)
        hd[t2][0] = hd[t2][1] = hd[t2][2] = hd[t2][3] = 0.f;
    #pragma unroll
    for (int kc = 0; kc < 16; ++kc) {
        const uint32_t a0 = hA[4 * kc], a1 = hA[4 * kc + 1];
        const uint32_t a2 = hA[4 * kc + 2], a3 = hA[4 * kc + 3];
        const uint32_t base = lds_w1 + kc * 16 * W1_STRIDE;
        #pragma unroll
        for (int nt2 = 0; nt2 < 4; ++nt2) {
            uint32_t b0, b1, b2, b3;
            ldsm4t(b0, b1, b2, b3, base + nt2 * 32);
            mma16816(hd[2 * nt2],     a0, a1, a2, a3, b0, b1);
            mma16816(hd[2 * nt2 + 1], a0, a1, a2, a3, b2, b3);
        }
    }
    {
        const float* sb1 = (const float*)(smem + OFF_B1);
        const float* sw2 = (const float*)(smem + OFF_W2);
        const float* sb2 = (const float*)(smem + OFF_B2);
        float acc0[5] = {0, 0, 0, 0, 0}, acc8[5] = {0, 0, 0, 0, 0};
        #pragma unroll
        for (int t2 = 0; t2 < 8; ++t2) {
            int c0 = 8 * t2 + 2 * tig;
            float b1a = sb1[c0], b1b = sb1[c0 + 1];
            float h00 = fmaxf(hd[t2][0] + b1a, 0.f), h01 = fmaxf(hd[t2][1] + b1b, 0.f);
            float h80 = fmaxf(hd[t2][2] + b1a, 0.f), h81 = fmaxf(hd[t2][3] + b1b, 0.f);
            #pragma unroll
            for (int c = 0; c < 5; ++c) {
                acc0[c] = fmaf(h00, sw2[c0 * 5 + c], fmaf(h01, sw2[(c0 + 1) * 5 + c], acc0[c]));
                acc8[c] = fmaf(h80, sw2[c0 * 5 + c], fmaf(h81, sw2[(c0 + 1) * 5 + c], acc8[c]));
            }
        }
        #pragma unroll
        for (int c = 0; c < 5; ++c) {                   // reduce over 4-lane tig group
            acc0[c] += __shfl_xor_sync(0xFFFFFFFFu, acc0[c], 1);
            acc0[c] += __shfl_xor_sync(0xFFFFFFFFu, acc0[c], 2);
            acc8[c] += __shfl_xor_sync(0xFFFFFFFFu, acc8[c], 1);
            acc8[c] += __shfl_xor_sync(0xFFFFFFFFu, acc8[c], 2);
        }
        if (tig == 0) {
            int row0 = m0 + wid * 16 + gid;
            float o[5];
            #pragma unroll
            for (int c = 0; c < 5; ++c) o[c] = acc0[c] + sb2[c];
            float mx = fmaxf(fmaxf(fmaxf(o[0], o[1]), fmaxf(o[2], o[3])), o[4]);
            float s = 0.f;
            #pragma unroll
            for (int c = 0; c < 5; ++c) { o[c] = __expf(o[c] - mx); s += o[c]; }
            float inv = 1.f / s;
            #pragma unroll
            for (int c = 0; c < 5; ++c) gout[(size_t)row0 * 5 + c] = o[c] * inv;

            #pragma unroll
            for (int c = 0; c < 5; ++c) o[c] = acc8[c] + sb2[c];
            mx = fmaxf(fmaxf(fmaxf(o[0], o[1]), fmaxf(o[2], o[3])), o[4]);
            s = 0.f;
            #pragma unroll
            for (int c = 0; c < 5; ++c) { o[c] = __expf(o[c] - mx); s += o[c]; }
            inv = 1.f / s;
            #pragma unroll
            for (int c = 0; c < 5; ++c) gout[(size_t)(row0 + 8) * 5 + c] = o[c] * inv;
        }
    }
}

// ---------------- launch ----------------
extern "C" void kernel_launch(void* const* d_in, const int* in_sizes, int n_in,
                              void* d_out, int out_size) {
    const float* x  = (const float*)d_in[0];
    const float* Wx = (const float*)d_in[1];
    const float* Wh = (const float*)d_in[2];
    const float* br = (const float*)d_in[3];
    const float* W1 = (const float*)d_in[4];
    const float* b1 = (const float*)d_in[5];
    const float* W2 = (const float*)d_in[6];
    const float* b2 = (const float*)d_in[7];

    cudaFuncSetAttribute(rnn_kernel, cudaFuncAttributeMaxDynamicSharedMemorySize, SMEM_TOTAL);
    rnn_kernel<<<256, NT, SMEM_TOTAL>>>(x, Wx, Wh, br, W1, b1, W2, b2, (float*)d_out);
}

// round 5
// speedup vs baseline: 1.4898x; 1.4898x over previous
#include <cuda_runtime.h>
#include <cuda_fp16.h>
#include <cstdint>

#define DINL __device__ __forceinline__

namespace {
constexpr int Tn = 187;
constexpr int Hn = 256;
constexpr int BM = 128;          // batch rows per CTA
constexpr int NT = 256;          // threads per CTA (8 warps x 16 rows)

constexpr int WH_STRIDE = 528;   // bytes per Wh row (264 f16: 512 + 16 pad -> conflict-free ldsm)
constexpr int W1_STRIDE = 144;   // bytes per W1 row (72 f16)
constexpr int X_STRIDE  = 192;   // f16 per x row

constexpr int OFF_WH  = 0;
constexpr int OFF_W1  = OFF_WH + Hn * WH_STRIDE;        // 135168
constexpr int OFF_X   = OFF_W1 + Hn * W1_STRIDE;        // 172032
constexpr int OFF_WXB = OFF_X  + BM * X_STRIDE * 2;     // 221184  (float2 {Wx,b} x256)
constexpr int OFF_B1  = OFF_WXB + Hn * 8;               // 223232
constexpr int OFF_W2  = OFF_B1 + 64 * 4;                // 223488
constexpr int OFF_B2  = OFF_W2 + 320 * 4;               // 224768
constexpr int SMEM_TOTAL = OFF_B2 + 32;                 // 224800
static_assert(SMEM_TOTAL <= 232448, "smem overflow");
}

// ---------------- helpers ----------------
DINL uint32_t smem_u32(const void* p) {
    uint32_t a;
    asm("{ .reg .u64 t; cvta.to.shared.u64 t, %1; cvt.u32.u64 %0, t; }" : "=r"(a) : "l"(p));
    return a;
}
// ldmatrix x4 transposed (B fragments for row.col mma from k-major smem)
DINL void ldsm4t(uint32_t& r0, uint32_t& r1, uint32_t& r2, uint32_t& r3, uint32_t addr) {
    asm volatile("ldmatrix.sync.aligned.m8n8.x4.trans.shared.b16 {%0,%1,%2,%3}, [%4];"
                 : "=r"(r0), "=r"(r1), "=r"(r2), "=r"(r3) : "r"(addr));
}
// D += A * B   (m16n8k16, f16 in, f32 accum)
DINL void mma16816(float* d, uint32_t a0, uint32_t a1, uint32_t a2, uint32_t a3,
                   uint32_t b0, uint32_t b1) {
    asm volatile("mma.sync.aligned.m16n8k16.row.col.f32.f16.f16.f32 "
                 "{%0,%1,%2,%3}, {%4,%5,%6,%7}, {%8,%9}, {%0,%1,%2,%3};"
                 : "+f"(d[0]), "+f"(d[1]), "+f"(d[2]), "+f"(d[3])
                 : "r"(a0), "r"(a1), "r"(a2), "r"(a3), "r"(b0), "r"(b1));
}
// pack {lo, hi} -> f16x2 (lo in bits[0:16))
DINL uint32_t pack_f16x2(float lo, float hi) {
    uint32_t r;
    asm("cvt.rn.f16x2.f32 %0, %1, %2;" : "=r"(r) : "f"(hi), "f"(lo));
    return r;
}
// 2-wide tanh on packed f16x2 (single MUFU op)
DINL uint32_t tanh2(uint32_t v) {
    uint32_t r;
    asm("tanh.approx.f16x2 %0, %1;" : "=r"(r) : "r"(v));
    return r;
}
// accurate f32 tanh (head-free path not needed; kept for t=0 nothing — unused)

// ---------------- kernel ----------------
__global__ void __launch_bounds__(NT, 1)
rnn_kernel(const float* __restrict__ gx,  const float* __restrict__ gWx,
           const float* __restrict__ gWh, const float* __restrict__ gbr,
           const float* __restrict__ gW1, const float* __restrict__ gb1,
           const float* __restrict__ gW2, const float* __restrict__ gb2,
           float* __restrict__ gout) {
    extern __shared__ char smem[];
    const int tid  = threadIdx.x;
    const int lane = tid & 31;
    const int wid  = tid >> 5;
    const int m0   = blockIdx.x * BM;
    const int gid  = lane >> 2;      // row group 0..7
    const int tig  = lane & 3;       // thread-in-group

    // ---- cooperative staging ----
    for (int i = tid; i < Hn * Hn; i += NT) {            // Wh[k][n] -> k-major padded f16
        int k = i >> 8, n = i & 255;
        *(__half*)(smem + OFF_WH + k * WH_STRIDE + n * 2) = __float2half(gWh[i]);
    }
    for (int i = tid; i < Hn * 64; i += NT) {            // W1[k][n]
        int k = i >> 6, n = i & 63;
        *(__half*)(smem + OFF_W1 + k * W1_STRIDE + n * 2) = __float2half(gW1[i]);
    }
    for (int i = tid; i < BM * Tn; i += NT) {            // x tile, f16
        int r = i / Tn, t = i - r * Tn;
        ((__half*)(smem + OFF_X))[r * X_STRIDE + t] = __float2half(gx[(size_t)(m0 + r) * Tn + t]);
    }
    for (int i = tid; i < Hn; i += NT)
        ((float2*)(smem + OFF_WXB))[i] = make_float2(gWx[i], gbr[i]);
    for (int i = tid; i < 64; i += NT)  ((float*)(smem + OFF_B1))[i] = gb1[i];
    for (int i = tid; i < 320; i += NT) ((float*)(smem + OFF_W2))[i] = gW2[i];
    if (tid < 5) ((float*)(smem + OFF_B2))[tid] = gb2[tid];
    __syncthreads();   // the ONLY barrier in the kernel

    // ---- per-warp setup ----
    const uint32_t sb = smem_u32(smem);
    const int tq = lane >> 3;   // ldmatrix x4 slot
    const uint32_t lds_wh = sb + OFF_WH + ((tq & 1) * 8 + (lane & 7)) * WH_STRIDE + (tq >> 1) * 16;
    const uint32_t lds_w1 = sb + OFF_W1 + ((tq & 1) * 8 + (lane & 7)) * W1_STRIDE + (tq >> 1) * 16;
    const __half* xr0 = (const __half*)(smem + OFF_X) + (wid * 16 + gid) * X_STRIDE;
    const __half* xr8 = xr0 + 8 * X_STRIDE;
    const float4* wxb4 = (const float4*)(smem + OFF_WXB);   // {w0,b0,w1,b1} per even col pair

    uint32_t hA[64];   // h as A fragments: hA[2t2]=(row gid, cols 8t2+2tig,+1), hA[2t2+1]=(+8 row)

    // ---- t = 0: h0 = tanh(x0*Wx + b) ----
    {
        float xg = __half2float(xr0[0]), xg8 = __half2float(xr8[0]);
        #pragma unroll
        for (int t2 = 0; t2 < 32; ++t2) {
            float4 wb = wxb4[(8 * t2 + 2 * tig) >> 1];
            hA[2 * t2]     = tanh2(pack_f16x2(fmaf(xg,  wb.x, wb.y), fmaf(xg,  wb.z, wb.w)));
            hA[2 * t2 + 1] = tanh2(pack_f16x2(fmaf(xg8, wb.x, wb.y), fmaf(xg8, wb.z, wb.w)));
        }
    }

    // ---- recurrence: t = 1..186 (warp-private, no sync) ----
    #pragma unroll 1
    for (int t = 1; t < Tn; ++t) {
        const float xg = __half2float(xr0[t]), xg8 = __half2float(xr8[t]);
        uint32_t held[64];                       // next-step A frags, committed at end of step
        #pragma unroll
        for (int g = 0; g < 4; ++g) {            // 64-col group: n8-tiles 8g..8g+7
            float d[8][4];
            #pragma unroll
            for (int j = 0; j < 8; ++j) {        // D init = x_t*Wx + b (folds epilogue add)
                float4 wb = wxb4[(8 * (8 * g + j) + 2 * tig) >> 1];
                d[j][0] = fmaf(xg,  wb.x, wb.y);
                d[j][1] = fmaf(xg,  wb.z, wb.w);
                d[j][2] = fmaf(xg8, wb.x, wb.y);
                d[j][3] = fmaf(xg8, wb.z, wb.w);
            }
            #pragma unroll
            for (int kc = 0; kc < 16; ++kc) {
                const uint32_t a0 = hA[4 * kc], a1 = hA[4 * kc + 1];
                const uint32_t a2 = hA[4 * kc + 2], a3 = hA[4 * kc + 3];
                const uint32_t base = lds_wh + kc * 16 * WH_STRIDE + g * 128;
                #pragma unroll
                for (int q = 0; q < 4; ++q) {    // nt2 = 4g+q -> tiles 8g+2q, 8g+2q+1
                    uint32_t b0, b1, b2, b3;
                    ldsm4t(b0, b1, b2, b3, base + q * 32);
                    mma16816(d[2 * q],     a0, a1, a2, a3, b0, b1);
                    mma16816(d[2 * q + 1], a0, a1, a2, a3, b2, b3);
                }
            }
            #pragma unroll
            for (int j = 0; j < 8; ++j) {        // pack -> 2-wide tanh -> held
                int t2 = 8 * g + j;
                held[2 * t2]     = tanh2(pack_f16x2(d[j][0], d[j][1]));
                held[2 * t2 + 1] = tanh2(pack_f16x2(d[j][2], d[j][3]));
            }
        }
        #pragma unroll
        for (int i = 0; i < 64; ++i) hA[i] = held[i];
    }

    // ---- head: hidden = relu(h @ W1 + b1) via mma, then W2 + softmax per thread ----
    float hd[8][4];
    #pragma unroll
    for (int t2 = 0; t2 < 8; ++t2)
        hd[t2][0] = hd[t2][1] = hd[t2][2] = hd[t2][3] = 0.f;
    #pragma unroll
    for (int kc = 0; kc < 16; ++kc) {
        const uint32_t a0 = hA[4 * kc], a1 = hA[4 * kc + 1];
        const uint32_t a2 = hA[4 * kc + 2], a3 = hA[4 * kc + 3];
        const uint32_t base = lds_w1 + kc * 16 * W1_STRIDE;
        #pragma unroll
        for (int nt2 = 0; nt2 < 4; ++nt2) {
            uint32_t b0, b1, b2, b3;
            ldsm4t(b0, b1, b2, b3, base + nt2 * 32);
            mma16816(hd[2 * nt2],     a0, a1, a2, a3, b0, b1);
            mma16816(hd[2 * nt2 + 1], a0, a1, a2, a3, b2, b3);
        }
    }
    {
        const float* sb1 = (const float*)(smem + OFF_B1);
        const float* sw2 = (const float*)(smem + OFF_W2);
        const float* sb2 = (const float*)(smem + OFF_B2);
        float acc0[5] = {0, 0, 0, 0, 0}, acc8[5] = {0, 0, 0, 0, 0};
        #pragma unroll
        for (int t2 = 0; t2 < 8; ++t2) {
            int c0 = 8 * t2 + 2 * tig;
            float b1a = sb1[c0], b1b = sb1[c0 + 1];
            float h00 = fmaxf(hd[t2][0] + b1a, 0.f), h01 = fmaxf(hd[t2][1] + b1b, 0.f);
            float h80 = fmaxf(hd[t2][2] + b1a, 0.f), h81 = fmaxf(hd[t2][3] + b1b, 0.f);
            #pragma unroll
            for (int c = 0; c < 5; ++c) {
                acc0[c] = fmaf(h00, sw2[c0 * 5 + c], fmaf(h01, sw2[(c0 + 1) * 5 + c], acc0[c]));
                acc8[c] = fmaf(h80, sw2[c0 * 5 + c], fmaf(h81, sw2[(c0 + 1) * 5 + c], acc8[c]));
            }
        }
        #pragma unroll
        for (int c = 0; c < 5; ++c) {                   // reduce over 4-lane tig group
            acc0[c] += __shfl_xor_sync(0xFFFFFFFFu, acc0[c], 1);
            acc0[c] += __shfl_xor_sync(0xFFFFFFFFu, acc0[c], 2);
            acc8[c] += __shfl_xor_sync(0xFFFFFFFFu, acc8[c], 1);
            acc8[c] += __shfl_xor_sync(0xFFFFFFFFu, acc8[c], 2);
        }
        if (tig == 0) {
            int row0 = m0 + wid * 16 + gid;
            float o[5];
            #pragma unroll
            for (int c = 0; c < 5; ++c) o[c] = acc0[c] + sb2[c];
            float mx = fmaxf(fmaxf(fmaxf(o[0], o[1]), fmaxf(o[2], o[3])), o[4]);
            float s = 0.f;
            #pragma unroll
            for (int c = 0; c < 5; ++c) { o[c] = __expf(o[c] - mx); s += o[c]; }
            float inv = 1.f / s;
            #pragma unroll
            for (int c = 0; c < 5; ++c) gout[(size_t)row0 * 5 + c] = o[c] * inv;

            #pragma unroll
            for (int c = 0; c < 5; ++c) o[c] = acc8[c] + sb2[c];
            mx = fmaxf(fmaxf(fmaxf(o[0], o[1]), fmaxf(o[2], o[3])), o[4]);
            s = 0.f;
            #pragma unroll
            for (int c = 0; c < 5; ++c) { o[c] = __expf(o[c] - mx); s += o[c]; }
            inv = 1.f / s;
            #pragma unroll
            for (int c = 0; c < 5; ++c) gout[(size_t)(row0 + 8) * 5 + c] = o[c] * inv;
        }
    }
}

// ---------------- launch ----------------
extern "C" void kernel_launch(void* const* d_in, const int* in_sizes, int n_in,
                              void* d_out, int out_size) {
    const float* x  = (const float*)d_in[0];
    const float* Wx = (const float*)d_in[1];
    const float* Wh = (const float*)d_in[2];
    const float* br = (const float*)d_in[3];
    const float* W1 = (const float*)d_in[4];
    const float* b1 = (const float*)d_in[5];
    const float* W2 = (const float*)d_in[6];
    const float* b2 = (const float*)d_in[7];

    cudaFuncSetAttribute(rnn_kernel, cudaFuncAttributeMaxDynamicSharedMemorySize, SMEM_TOTAL);
    rnn_kernel<<<256, NT, SMEM_TOTAL>>>(x, Wx, Wh, br, W1, b1, W2, b2, (float*)d_out);
}